// round 12
// baseline (speedup 1.0000x reference)
#include <cuda_runtime.h>
#include <cuda_fp16.h>
#include <cstdint>

#define N_NODES 50000
#define N_EDGES 800000
#define D_IN    256
#define D_OUT   128

#define SCAN_BLOCKS ((N_NODES + 1023) / 1024)   // 49

// ---------------- scratch (no allocations allowed) ----------------
// deg and bsum share one region -> one memset
__device__ int    g_scratch[N_NODES + 64];      // [0,N) deg, [N,N+64) bsum
__device__ float  g_dinv  [N_NODES];
__device__ int    g_rowptr[N_NODES + 1];
__device__ int    g_cursor[N_NODES];
__device__ int2   g_edge  [N_EDGES];            // {src, __float_as_int(dinv[src])}
__device__ __align__(16) __half g_h[(size_t)N_NODES * D_OUT];   // 12.8 MB

// ---------------- streams/events (created before capture) ----------------
static cudaStream_t g_s2;
static cudaEvent_t  g_evFork, g_evJoin;
static struct StreamInit {
    StreamInit() {
        cudaStreamCreateWithFlags(&g_s2, cudaStreamNonBlocking);
        cudaEventCreateWithFlags(&g_evFork, cudaEventDisableTiming);
        cudaEventCreateWithFlags(&g_evJoin, cudaEventDisableTiming);
    }
} g_streamInit;

// ---------------- 1. histogram of dst (x4 vectorized) ----------------
__global__ void k_count(const int4* __restrict__ dst4, int* deg) {
    int e = blockIdx.x * blockDim.x + threadIdx.x;
    if (e < N_EDGES / 4) {
        int4 d = dst4[e];
        atomicAdd(&deg[d.x], 1);
        atomicAdd(&deg[d.y], 1);
        atomicAdd(&deg[d.z], 1);
        atomicAdd(&deg[d.w], 1);
    }
}

// ---------------- 2. fused scan: decoupled lookback (49 co-resident blocks) -
__global__ __launch_bounds__(256) void k_scanf(const int* __restrict__ deg,
                                               int* bsum,     // zeroed, publish s+1
                                               int* __restrict__ rowptr,
                                               int* __restrict__ cursor,
                                               float* __restrict__ dinv) {
    __shared__ int ws[8];
    __shared__ int woff[8];
    __shared__ int pred[64];
    __shared__ int boffs;

    int b = blockIdx.x, t = threadIdx.x;
    int lane = t & 31, w = t >> 5;
    int base = b * 1024 + t * 4;

    int d[4];
    int s = 0;
#pragma unroll
    for (int q = 0; q < 4; q++) {
        int i = base + q;
        d[q] = (i < N_NODES) ? deg[i] : 0;
        s += d[q];
    }
    int inc = s;
    for (int o = 1; o < 32; o <<= 1) {
        int v = __shfl_up_sync(0xffffffffu, inc, o);
        if (lane >= o) inc += v;
    }
    if (lane == 31) ws[w] = inc;
    if (t < 64) pred[t] = 0;
    __syncthreads();

    if (t < 8) {
        int v = ws[t];
        int p = v;
        for (int o = 1; o < 8; o <<= 1) {
            int u = __shfl_up_sync(0xffu, p, o);
            if (t >= o) p += u;
        }
        woff[t] = p - v;
        if (t == 7) {
            __threadfence();
            atomicExch(&bsum[b], p + 1);
        }
    }
    if (t < b) {
        int v;
        do { v = *((volatile int*)&bsum[t]); } while (v == 0);
        pred[t] = v - 1;
    }
    __syncthreads();
    if (t < 32) {
        int ss = pred[t] + pred[t + 32];
        for (int o = 16; o; o >>= 1) ss += __shfl_down_sync(0xffffffffu, ss, o);
        if (t == 0) boffs = ss;
    }
    __syncthreads();

    int off = boffs + woff[w] + (inc - s);
#pragma unroll
    for (int q = 0; q < 4; q++) {
        int i = base + q;
        if (i < N_NODES) {
            rowptr[i] = off;
            cursor[i] = off;
            dinv[i]   = rsqrtf((float)d[q] + 1.0f);   // +1 = self loop
            off += d[q];
        }
    }
    if (b == 0 && t == 0) rowptr[N_NODES] = N_EDGES;
}

// ---------------- 3. bucket fill x4: {src, dinv[src]} ----------------
__global__ void k_fill(const int4* __restrict__ src4,
                       const int4* __restrict__ dst4,
                       int* __restrict__ cursor,
                       const float* __restrict__ dinv,
                       int2* __restrict__ edge) {
    int e = blockIdx.x * blockDim.x + threadIdx.x;
    if (e < N_EDGES / 4) {
        int4 s = src4[e];
        int4 d = dst4[e];
        float f0 = dinv[s.x];
        float f1 = dinv[s.y];
        float f2 = dinv[s.z];
        float f3 = dinv[s.w];
        int p0 = atomicAdd(&cursor[d.x], 1);
        int p1 = atomicAdd(&cursor[d.y], 1);
        int p2 = atomicAdd(&cursor[d.z], 1);
        int p3 = atomicAdd(&cursor[d.w], 1);
        edge[p0] = make_int2(s.x, __float_as_int(f0));
        edge[p1] = make_int2(s.y, __float_as_int(f1));
        edge[p2] = make_int2(s.z, __float_as_int(f2));
        edge[p3] = make_int2(s.w, __float_as_int(f3));
    }
}

// ---------------- 4. GEMM h = x @ W, fp16 mma.sync ----------
// block tile 64x128; A tile loaded ONCE (fp16, 64x256, stride 264), B dbuf.
#define A_ST      264                  // halves per row (256 + 8 pad)
#define BS_STAGE  (8 * 132)            // half2 per stage

__global__ __launch_bounds__(256, 4) void k_gemm16(const float* __restrict__ X,
                                                   const float* __restrict__ W,
                                                   __half* __restrict__ H) {
    __shared__ __half As[64 * A_ST];       // 33792 B
    __shared__ half2  Bs[2][BS_STAGE];     // 8448 B

    const int tid  = threadIdx.x;
    const int warp = tid >> 5;
    const int lane = tid & 31;
    const int g    = lane >> 2;      // 0..7
    const int tig  = lane & 3;       // 0..3
    const int m0   = blockIdx.x * 64;
    const int mrow = (warp >> 1) * 16;   // 0,16,32,48
    const int ncol = (warp & 1) * 64;    // 0 or 64

    const float4* X4 = (const float4*)X;   // row stride 64
    const float4* W4 = (const float4*)W;   // row stride 32

    // B loader indices
    const int bkp = tid >> 5;        // 0..7   k-pair row
    const int bn4 = tid & 31;        // 0..31  float4 col

    // ---- load FULL A tile (64 rows x 256 cols), coalesced, convert fp16
#pragma unroll
    for (int p = 0; p < 16; p++) {
        int idx = tid + p * 256;           // 0..4095
        int r   = idx >> 6;                // 0..63
        int c4  = idx & 63;                // 0..63 float4 within row
        int gr  = m0 + r;
        float4 v = make_float4(0.f, 0.f, 0.f, 0.f);
        if (gr < N_NODES) v = X4[(size_t)gr * 64 + c4];
        half2 h01 = __floats2half2_rn(v.x, v.y);
        half2 h23 = __floats2half2_rn(v.z, v.w);
        uint2 u; u.x = *(unsigned*)&h01; u.y = *(unsigned*)&h23;
        *(uint2*)(&As[r * A_ST + c4 * 4]) = u;
    }

    // ---- B stage 0
    {
        float4 a = W4[(size_t)(2 * bkp) * 32 + bn4];
        float4 c = W4[(size_t)(2 * bkp + 1) * 32 + bn4];
        half2 p0 = __floats2half2_rn(a.x, c.x);
        half2 p1 = __floats2half2_rn(a.y, c.y);
        half2 p2 = __floats2half2_rn(a.z, c.z);
        half2 p3 = __floats2half2_rn(a.w, c.w);
        uint4 pk;
        pk.x = *(unsigned*)&p0; pk.y = *(unsigned*)&p1;
        pk.z = *(unsigned*)&p2; pk.w = *(unsigned*)&p3;
        *(uint4*)(&Bs[0][bkp * 132 + bn4 * 4]) = pk;
    }
    __syncthreads();

    float acc[8][4];
#pragma unroll
    for (int nt = 0; nt < 8; nt++)
#pragma unroll
        for (int j = 0; j < 4; j++) acc[nt][j] = 0.0f;

    int buf = 0;
#pragma unroll 1
    for (int ks = 0; ks < 16; ks++) {
        // reg-prefetch next B chunk
        float4 preB0, preB1;
        if (ks + 1 < 16) {
            int k0n = (ks + 1) * 16;
            preB0 = W4[(size_t)(k0n + 2 * bkp) * 32 + bn4];
            preB1 = W4[(size_t)(k0n + 2 * bkp + 1) * 32 + bn4];
        }

        // A fragments (m16 k16) from resident tile
        const int kb = ks * 16;
        const __half* Ab = &As[0];
        int r = mrow + g;
        unsigned a0 = *(const unsigned*)(Ab + r * A_ST + kb + 2 * tig);
        unsigned a1 = *(const unsigned*)(Ab + (r + 8) * A_ST + kb + 2 * tig);
        unsigned a2 = *(const unsigned*)(Ab + r * A_ST + kb + 2 * tig + 8);
        unsigned a3 = *(const unsigned*)(Ab + (r + 8) * A_ST + kb + 2 * tig + 8);

#pragma unroll
        for (int nt = 0; nt < 8; nt++) {
            int n0 = ncol + nt * 8;
            unsigned b0 = *(const unsigned*)&Bs[buf][tig * 132 + n0 + g];
            unsigned b1 = *(const unsigned*)&Bs[buf][(tig + 4) * 132 + n0 + g];
            asm volatile(
                "mma.sync.aligned.m16n8k16.row.col.f32.f16.f16.f32 "
                "{%0,%1,%2,%3}, {%4,%5,%6,%7}, {%8,%9}, {%0,%1,%2,%3};\n"
                : "+f"(acc[nt][0]), "+f"(acc[nt][1]),
                  "+f"(acc[nt][2]), "+f"(acc[nt][3])
                : "r"(a0), "r"(a1), "r"(a2), "r"(a3), "r"(b0), "r"(b1));
        }

        if (ks + 1 < 16) {
            int nbuf = buf ^ 1;
            half2 p0 = __floats2half2_rn(preB0.x, preB1.x);
            half2 p1 = __floats2half2_rn(preB0.y, preB1.y);
            half2 p2 = __floats2half2_rn(preB0.z, preB1.z);
            half2 p3 = __floats2half2_rn(preB0.w, preB1.w);
            uint4 pk;
            pk.x = *(unsigned*)&p0; pk.y = *(unsigned*)&p1;
            pk.z = *(unsigned*)&p2; pk.w = *(unsigned*)&p3;
            *(uint4*)(&Bs[nbuf][bkp * 132 + bn4 * 4]) = pk;
            __syncthreads();
            buf = nbuf;
        }
    }

    // ---- epilogue: fp32 acc -> fp16 H (unscaled)
    int r0 = m0 + mrow + g;
#pragma unroll
    for (int nt = 0; nt < 8; nt++) {
        int col = ncol + nt * 8 + 2 * tig;
        half2 lo = __floats2half2_rn(acc[nt][0], acc[nt][1]);
        half2 hi = __floats2half2_rn(acc[nt][2], acc[nt][3]);
        if (r0 < N_NODES)
            *(unsigned*)(H + (size_t)r0 * 128 + col) = *(unsigned*)&lo;
        if (r0 + 8 < N_NODES)
            *(unsigned*)(H + (size_t)(r0 + 8) * 128 + col) = *(unsigned*)&hi;
    }
}

// ---------------- 5. gather (fp16 rows) + self-loop + bias + PReLU ----------
__global__ __launch_bounds__(256) void k_gather(const int* __restrict__ rowptr,
                                                const int2* __restrict__ edge,
                                                const float* __restrict__ dinv,
                                                const __half* __restrict__ H,
                                                const float* __restrict__ b,
                                                const float* __restrict__ pa,
                                                float* __restrict__ out) {
    int node = blockIdx.x * 8 + (threadIdx.x >> 5);
    int lane = threadIdx.x & 31;
    if (node >= N_NODES) return;

    const uint2* H2 = (const uint2*)H;
    float di = dinv[node];

    uint2 sraw = __ldcg(&H2[(size_t)node * 32 + lane]);
    float2 s01 = __half22float2(*reinterpret_cast<const __half2*>(&sraw.x));
    float2 s23 = __half22float2(*reinterpret_cast<const __half2*>(&sraw.y));
    float4 acc = make_float4(s01.x * di, s01.y * di, s23.x * di, s23.y * di);

    int r0 = rowptr[node];
    int r1 = rowptr[node + 1];

    for (int base = r0; base < r1; base += 32) {
        int e   = base + lane;
        int2 eL = (e < r1) ? __ldcs(&edge[e]) : make_int2(0, 0);
        int cnt = min(32, r1 - base);

        int j = 0;
        for (; j + 8 <= cnt; j += 8) {
            uint2 v[8];
            float sc[8];
#pragma unroll
            for (int t = 0; t < 8; t++) {
                int src = __shfl_sync(0xffffffffu, eL.x, j + t);
                sc[t]   = __int_as_float(__shfl_sync(0xffffffffu, eL.y, j + t));
                v[t]    = __ldcg(&H2[(size_t)src * 32 + lane]);
            }
#pragma unroll
            for (int t = 0; t < 8; t++) {
                float2 f01 = __half22float2(*reinterpret_cast<const __half2*>(&v[t].x));
                float2 f23 = __half22float2(*reinterpret_cast<const __half2*>(&v[t].y));
                acc.x += f01.x * sc[t];
                acc.y += f01.y * sc[t];
                acc.z += f23.x * sc[t];
                acc.w += f23.y * sc[t];
            }
        }
        for (; j + 4 <= cnt; j += 4) {
            uint2 v[4];
            float sc[4];
#pragma unroll
            for (int t = 0; t < 4; t++) {
                int src = __shfl_sync(0xffffffffu, eL.x, j + t);
                sc[t]   = __int_as_float(__shfl_sync(0xffffffffu, eL.y, j + t));
                v[t]    = __ldcg(&H2[(size_t)src * 32 + lane]);
            }
#pragma unroll
            for (int t = 0; t < 4; t++) {
                float2 f01 = __half22float2(*reinterpret_cast<const __half2*>(&v[t].x));
                float2 f23 = __half22float2(*reinterpret_cast<const __half2*>(&v[t].y));
                acc.x += f01.x * sc[t];
                acc.y += f01.y * sc[t];
                acc.z += f23.x * sc[t];
                acc.w += f23.y * sc[t];
            }
        }
        for (; j < cnt; j++) {
            int   src = __shfl_sync(0xffffffffu, eL.x, j);
            float sc  = __int_as_float(__shfl_sync(0xffffffffu, eL.y, j));
            uint2 v   = __ldcg(&H2[(size_t)src * 32 + lane]);
            float2 f01 = __half22float2(*reinterpret_cast<const __half2*>(&v.x));
            float2 f23 = __half22float2(*reinterpret_cast<const __half2*>(&v.y));
            acc.x += f01.x * sc;
            acc.y += f01.y * sc;
            acc.z += f23.x * sc;
            acc.w += f23.y * sc;
        }
    }

    float4 bb = ((const float4*)b)[lane];
    float4 aa = ((const float4*)pa)[lane];
    float4 o;
    o.x = acc.x * di + bb.x;
    o.y = acc.y * di + bb.y;
    o.z = acc.z * di + bb.z;
    o.w = acc.w * di + bb.w;
    o.x = o.x > 0.f ? o.x : aa.x * o.x;
    o.y = o.y > 0.f ? o.y : aa.y * o.y;
    o.z = o.z > 0.f ? o.z : aa.z * o.z;
    o.w = o.w > 0.f ? o.w : aa.w * o.w;
    __stcs(&((float4*)out)[(size_t)node * 32 + lane], o);
}

// ---------------- launch ----------------
extern "C" void kernel_launch(void* const* d_in, const int* in_sizes, int n_in,
                              void* d_out, int out_size) {
    const float* x  = (const float*)d_in[0];
    const int*   ei = (const int*)d_in[1];     // [2, N_EDGES] int32
    const float* W  = (const float*)d_in[2];
    const float* b  = (const float*)d_in[3];
    const float* pa = (const float*)d_in[4];
    float* out = (float*)d_out;

    int*    scratch; cudaGetSymbolAddress((void**)&scratch, g_scratch);
    float*  dinv;    cudaGetSymbolAddress((void**)&dinv,    g_dinv);
    int*    rowptr;  cudaGetSymbolAddress((void**)&rowptr,  g_rowptr);
    int*    cursor;  cudaGetSymbolAddress((void**)&cursor,  g_cursor);
    int2*   edge;    cudaGetSymbolAddress((void**)&edge,    g_edge);
    __half* h;       cudaGetSymbolAddress((void**)&h,       g_h);

    int* deg  = scratch;
    int* bsum = scratch + N_NODES;

    cudaEventRecord(g_evFork, 0);
    cudaStreamWaitEvent(g_s2, g_evFork, 0);

    // build chain on s2
    cudaMemsetAsync(scratch, 0, (N_NODES + 64) * sizeof(int), g_s2);
    k_count<<<(N_EDGES / 4 + 255) / 256, 256, 0, g_s2>>>(
        (const int4*)(ei + N_EDGES), deg);
    k_scanf<<<SCAN_BLOCKS, 256, 0, g_s2>>>(deg, bsum, rowptr, cursor, dinv);
    k_fill <<<(N_EDGES / 4 + 255) / 256, 256, 0, g_s2>>>(
        (const int4*)ei, (const int4*)(ei + N_EDGES), cursor, dinv, edge);
    cudaEventRecord(g_evJoin, g_s2);

    // GEMM on capture stream, no deps — overlaps entire build
    k_gemm16<<<(N_NODES + 63) / 64, 256>>>(x, W, h);

    cudaStreamWaitEvent(0, g_evJoin, 0);
    k_gather<<<(N_NODES + 7) / 8, 256>>>(rowptr, edge, dinv, h, b, pa, out);
}